// round 15
// baseline (speedup 1.0000x reference)
#include <cuda_runtime.h>
#include <cuda_fp16.h>
#include <cstdint>
#include <math.h>

// ---------------- problem constants ----------------
constexpr int  B_   = 8;
constexpr int  C_   = 256;
constexpr int  H_   = 200;
constexpr int  W_   = 200;
constexpr int  WS_  = 7;
constexpr int  HP_  = 203;
constexpr int  WP_  = 203;
constexpr int  NWH  = 29;
constexpr int  NWW  = 29;
constexpr int  NWIN = B_ * NWH * NWW;              // 6728
constexpr size_t M_TOT = (size_t)B_ * HP_ * WP_;   // 329672 real tokens
constexpr int  MTILES = 2576;                      // ceil(M_TOT/128)
constexpr size_t M_PAD = (size_t)MTILES * 128;     // 329728 (GEMMs run guard-free)

// ---------------- scratch (device globals; zero-initialized) ----------------
__device__ float   g_xpad[M_PAD * 256];   // residual s = x + pos (fp32, channels-last)
__device__ __half  g_z   [M_PAD * 256];
__device__ __half  g_qkv [M_PAD * 768];
__device__ __half  g_o   [M_PAD * 256];
__device__ float   g_s2  [M_PAD * 256];   // s + attn proj (fp32 residual stream)
__device__ __half  g_h   [M_PAD * 256];
__device__ __half  g_g   [M_PAD * 1024];

__device__ __half  g_wqkv[768 * 256];
__device__ __half  g_wo  [256 * 256];
__device__ __half  g_w1  [1024 * 256];
__device__ __half  g_w2  [256 * 1024];

// ---------------- low-level helpers ----------------
__device__ __forceinline__ void cp16(void* s, const void* g) {
    unsigned sa = (unsigned)__cvta_generic_to_shared(s);
    asm volatile("cp.async.cg.shared.global [%0], [%1], 16;\n" :: "r"(sa), "l"(g));
}
__device__ __forceinline__ void cp_commit() { asm volatile("cp.async.commit_group;\n"); }
__device__ __forceinline__ void cp_wait1()  { asm volatile("cp.async.wait_group 1;\n"); }

__device__ __forceinline__ uint32_t smem_u32(const void* p) {
    return (uint32_t)__cvta_generic_to_shared(p);
}

// fp16 in, fp16 acc
__device__ __forceinline__ void mma16816h(unsigned* d,
                                          unsigned a0, unsigned a1, unsigned a2, unsigned a3,
                                          unsigned b0, unsigned b1) {
    asm volatile("mma.sync.aligned.m16n8k16.row.col.f16.f16.f16.f16 "
                 "{%0,%1}, {%2,%3,%4,%5}, {%6,%7}, {%0,%1};"
                 : "+r"(d[0]), "+r"(d[1])
                 : "r"(a0), "r"(a1), "r"(a2), "r"(a3), "r"(b0), "r"(b1));
}

// fp16 in, fp32 acc (attention softmax path)
__device__ __forceinline__ void mma16816f(float* d,
                                          unsigned a0, unsigned a1, unsigned a2, unsigned a3,
                                          unsigned b0, unsigned b1) {
    asm volatile("mma.sync.aligned.m16n8k16.row.col.f32.f16.f16.f32 "
                 "{%0,%1,%2,%3}, {%4,%5,%6,%7}, {%8,%9}, {%0,%1,%2,%3};"
                 : "+f"(d[0]), "+f"(d[1]), "+f"(d[2]), "+f"(d[3])
                 : "r"(a0), "r"(a1), "r"(a2), "r"(a3), "r"(b0), "r"(b1));
}

__device__ __forceinline__ void ldsm_x4(unsigned& r0, unsigned& r1, unsigned& r2, unsigned& r3,
                                        uint32_t addr) {
    asm volatile("ldmatrix.sync.aligned.m8n8.x4.shared.b16 {%0,%1,%2,%3}, [%4];"
                 : "=r"(r0), "=r"(r1), "=r"(r2), "=r"(r3) : "r"(addr));
}

// ---------------- diagnostic no-op (keeps ncu's slot on the QKV GEMM) ----------
__global__ void noop_kernel() {}

// ---------------- fused fp32 -> fp16 weight convert ----------------
__global__ void cvt_all_kernel(const float* __restrict__ a0, const float* __restrict__ a1,
                               const float* __restrict__ a2, const float* __restrict__ a3,
                               __half* __restrict__ o0, __half* __restrict__ o1,
                               __half* __restrict__ o2, __half* __restrict__ o3) {
    int i = blockIdx.x * 256 + threadIdx.x;
    if (i < 196608)       o0[i] = __float2half(a0[i]);
    else if (i < 262144)  o1[i - 196608] = __float2half(a1[i - 196608]);
    else if (i < 524288)  o2[i - 262144] = __float2half(a2[i - 262144]);
    else if (i < 786432)  o3[i - 524288] = __float2half(a3[i - 524288]);
}

// ---------------- fused NCHW->channels-last pad transpose + LN1 ----------------
__global__ void __launch_bounds__(256) lnin_kernel(
    const float* __restrict__ x, const float* __restrict__ pos,
    const float* __restrict__ gw, const float* __restrict__ gb,
    float* __restrict__ xp, __half* __restrict__ z)
{
    __shared__ float tile[256][33];
    const int tx = threadIdx.x, ty = threadIdx.y;
    const int h = blockIdx.y, b = blockIdx.z;
    const int w = blockIdx.x * 32 + tx;
    const bool hv = h < H_;
    const bool wv = w < W_;
#pragma unroll
    for (int j = 0; j < 32; j++) {
        int c = ty + 8 * j;
        float v = 0.f;
        if (hv && wv) v = x[(((size_t)b * 256 + c) * 200 + h) * 200 + w];
        tile[c][tx] = v;
    }
    __syncthreads();

    const int lane = tx;
    for (int tk = ty; tk < 32; tk += 8) {
        int wtok = blockIdx.x * 32 + tk;
        if (wtok >= WP_) break;
        size_t m = ((size_t)(b * HP_ + h)) * WP_ + wtok;
        int t = (h % WS_) * WS_ + (wtok % WS_);
        float v[8];
        float s = 0.f, sq = 0.f;
#pragma unroll
        for (int i = 0; i < 8; i++) {
            int c = lane + 32 * i;
            float vv = tile[c][tk] + pos[(size_t)t * 256 + c];
            v[i] = vv;
            xp[m * 256 + c] = vv;
            s += vv; sq += vv * vv;
        }
#pragma unroll
        for (int o = 16; o; o >>= 1) {
            s  += __shfl_xor_sync(0xffffffffu, s,  o);
            sq += __shfl_xor_sync(0xffffffffu, sq, o);
        }
        float mean = s * (1.f / 256.f);
        float var  = sq * (1.f / 256.f) - mean * mean;
        float inv  = rsqrtf(var + 1e-5f);
#pragma unroll
        for (int i = 0; i < 8; i++) {
            int c = lane + 32 * i;
            z[m * 256 + c] = __float2half((v[i] - mean) * inv * gw[c] + gb[c]);
        }
    }
}

// ---------------- LayerNorm (LN2): one warp per token, fp32 in ----------------
__global__ void __launch_bounds__(256) ln_kernel(
    const float* __restrict__ in,
    const float* __restrict__ gw, const float* __restrict__ gb,
    __half* __restrict__ out, int M)
{
    int m = blockIdx.x * 8 + (threadIdx.x >> 5);
    int lane = threadIdx.x & 31;
    if (m >= M) return;
    size_t base = (size_t)m * 256 + lane * 8;
    float4 a0 = *(const float4*)(in + base);
    float4 a1 = *(const float4*)(in + base + 4);
    float v[8] = {a0.x, a0.y, a0.z, a0.w, a1.x, a1.y, a1.z, a1.w};
    float s = 0.f, sq = 0.f;
#pragma unroll
    for (int i = 0; i < 8; i++) { s += v[i]; sq += v[i] * v[i]; }
#pragma unroll
    for (int o = 16; o; o >>= 1) {
        s  += __shfl_xor_sync(0xffffffffu, s,  o);
        sq += __shfl_xor_sync(0xffffffffu, sq, o);
    }
    float mean = s * (1.f / 256.f);
    float var  = sq * (1.f / 256.f) - mean * mean;
    float inv  = rsqrtf(var + 1e-5f);
    float4 w0 = *(const float4*)(gw + lane * 8);
    float4 w1 = *(const float4*)(gw + lane * 8 + 4);
    float4 b0 = *(const float4*)(gb + lane * 8);
    float4 b1 = *(const float4*)(gb + lane * 8 + 4);
    float wv[8] = {w0.x, w0.y, w0.z, w0.w, w1.x, w1.y, w1.z, w1.w};
    float bv[8] = {b0.x, b0.y, b0.z, b0.w, b1.x, b1.y, b1.z, b1.w};
    union { uint4 u; __half h[8]; } pk;
#pragma unroll
    for (int i = 0; i < 8; i++)
        pk.h[i] = __float2half((v[i] - mean) * inv * wv[i] + bv[i]);
    *(uint4*)(out + base) = pk.u;
}

// ---------------- raw-mma fp16 GEMM  C = A(MxK) * W(NxK)^T ----------------
// CTA tile 128x256, 128 threads (4 warps; warp tile 64x128 -> 1.125 wf/MMA),
// BK=64, 2-stage cp.async double buffer, 96KB smem -> 2 CTAs/SM.
constexpr int GM_STAGE = 49152;             // A 16KB + B 32KB
constexpr int GM_SMEM  = 2 * GM_STAGE;      // 98304

// EPI 0: qkv  (scale q cols, -> half)
// EPI 1: proj (acc + bias + resid(xpad f32) -> f32 s2)
// EPI 2: ff1  (gelu -> half)
// EPI 3: ff2  (acc + bias + resid(s2 f32) -> fp32 NCHW cropped out)
template <int EPI>
__global__ void __launch_bounds__(128, 2) gemm_mma(
    const __half* __restrict__ A, const __half* __restrict__ Wt,
    const float* __restrict__ bias, int K, int NOUT,
    __half* __restrict__ outb, float* __restrict__ outf,
    const float* __restrict__ resid)
{
    extern __shared__ char sm[];
    const uint32_t sb = smem_u32(sm);
    const int tid = threadIdx.x;
    const int wid = tid >> 5, lane = tid & 31;
    const int g = lane >> 2, c = lane & 3;
    const int wm = wid >> 1, wn = wid & 1;         // wm 0..1 (64 rows), wn 0..1 (128 cols)
    const int n0 = blockIdx.x * 256;
    const size_t m0 = (size_t)blockIdx.y * 128;

    const __half* gA = A + m0 * K;
    const __half* gB = Wt + (size_t)n0 * K;

    auto fill = [&](int kt, int st) {
        char* ab = sm + st * GM_STAGE;
#pragma unroll
        for (int it = 0; it < 8; it++) {          // A: 128x64 (1024 chunks)
            int idx = tid + it * 128;
            int r = idx >> 3, c16 = idx & 7;
            cp16(ab + r * 128 + ((c16 ^ (r & 7)) << 4),
                 gA + (size_t)r * K + kt * 64 + c16 * 8);
        }
#pragma unroll
        for (int it = 0; it < 16; it++) {         // B: 256x64 (2048 chunks)
            int idx = tid + it * 128;
            int r = idx >> 3, c16 = idx & 7;
            cp16(ab + 16384 + r * 128 + ((c16 ^ (r & 7)) << 4),
                 gB + (size_t)r * K + kt * 64 + c16 * 8);
        }
        cp_commit();
    };

    unsigned acc[4][16][2];
#pragma unroll
    for (int mi = 0; mi < 4; mi++)
#pragma unroll
        for (int nt = 0; nt < 16; nt++) { acc[mi][nt][0] = 0u; acc[mi][nt][1] = 0u; }

    const int KC = K / 64;
    fill(0, 0); fill(1, 1);

    const int a_row_lo = lane & 15;
    const int a_ch_half = lane >> 4;
    const int b_tile = lane >> 3;
    const int b_row  = lane & 7;

    for (int kt = 0; kt < KC; kt++) {
        cp_wait1();
        __syncthreads();
        const uint32_t ab  = sb + (kt & 1) * GM_STAGE;
        const uint32_t bbm = ab + 16384;
#pragma unroll
        for (int kk = 0; kk < 4; kk++) {
            unsigned afr[4][4];
#pragma unroll
            for (int mi = 0; mi < 4; mi++) {
                int row = wm * 64 + mi * 16 + a_row_lo;
                int ch  = kk * 2 + a_ch_half;
                ldsm_x4(afr[mi][0], afr[mi][1], afr[mi][2], afr[mi][3],
                        ab + row * 128 + (uint32_t)((ch ^ (row & 7)) << 4));
            }
#pragma unroll
            for (int np = 0; np < 8; np++) {
                int n = wn * 128 + np * 16 + ((b_tile >> 1) << 3) + b_row;
                int chunk = kk * 2 + (b_tile & 1);
                unsigned bfr0, bfr1, bfr2, bfr3;
                ldsm_x4(bfr0, bfr1, bfr2, bfr3,
                        bbm + n * 128 + (uint32_t)((chunk ^ b_row) << 4));
#pragma unroll
                for (int mi = 0; mi < 4; mi++) {
                    mma16816h(acc[mi][2 * np],     afr[mi][0], afr[mi][1], afr[mi][2], afr[mi][3], bfr0, bfr1);
                    mma16816h(acc[mi][2 * np + 1], afr[mi][0], afr[mi][1], afr[mi][2], afr[mi][3], bfr2, bfr3);
                }
            }
        }
        __syncthreads();
        if (kt + 2 < KC) fill(kt + 2, kt & 1);
        else             cp_commit();              // empty group keeps accounting exact
    }

    // ---------- epilogues ----------
    if (EPI == 0 || EPI == 2) {
        const float scale = (EPI == 0 && n0 == 0) ? 0.17677669529663689f : 1.f;
#pragma unroll
        for (int nt = 0; nt < 16; nt++) {
            int cb = n0 + wn * 128 + nt * 8 + 2 * c;
            float2 b2 = *(const float2*)(bias + cb);
#pragma unroll
            for (int mi = 0; mi < 4; mi++) {
                size_t r0 = m0 + wm * 64 + mi * 16 + g;
#pragma unroll
                for (int half = 0; half < 2; half++) {
                    size_t r = r0 + 8 * half;
                    float2 f = __half22float2(*(__half2*)&acc[mi][nt][half]);
                    float vx = f.x + b2.x;
                    float vy = f.y + b2.y;
                    if (EPI == 0) { vx *= scale; vy *= scale; }
                    else {
                        vx = 0.5f * vx * (1.f + erff(vx * 0.7071067811865475f));
                        vy = 0.5f * vy * (1.f + erff(vy * 0.7071067811865475f));
                    }
                    __half2 pk2 = __floats2half2_rn(vx, vy);
                    *(unsigned*)(outb + r * NOUT + cb) = *(unsigned*)&pk2;
                }
            }
        }
    } else if (EPI == 1) {
#pragma unroll
        for (int mi = 0; mi < 4; mi++)
#pragma unroll
            for (int half = 0; half < 2; half++) {
                size_t m = m0 + wm * 64 + mi * 16 + g + 8 * half;
#pragma unroll
                for (int nt = 0; nt < 16; nt++) {
                    int cb = n0 + wn * 128 + nt * 8 + 2 * c;
                    float2 b2 = *(const float2*)(bias + cb);
                    float2 rs = *(const float2*)(resid + m * 256 + cb);
                    float2 f = __half22float2(*(__half2*)&acc[mi][nt][half]);
                    float2 ov;
                    ov.x = f.x + b2.x + rs.x;
                    ov.y = f.y + b2.y + rs.y;
                    *(float2*)(outf + m * 256 + cb) = ov;
                }
            }
    } else {
        // EPI 3: two 64-row halves through Cs (64 x 260 f32 = 66560 <= 96KB)
        float* Cs = (float*)sm;
#pragma unroll
        for (int hblk = 0; hblk < 2; hblk++) {
            __syncthreads();
#pragma unroll
            for (int nt = 0; nt < 16; nt++) {
                int cl = wn * 128 + nt * 8 + 2 * c;
                float2 b2 = *(const float2*)(bias + n0 + cl);
#pragma unroll
                for (int mi = 0; mi < 4; mi++) {
                    int rloc = wm * 64 + mi * 16 + g;      // 0..127 (rloc,rloc+8 same 64-block)
                    if ((rloc >> 6) == hblk) {
                        int r0 = rloc & 63;
                        float2 f0 = __half22float2(*(__half2*)&acc[mi][nt][0]);
                        float2 f1 = __half22float2(*(__half2*)&acc[mi][nt][1]);
                        Cs[(r0)     * 260 + cl]     = f0.x + b2.x;
                        Cs[(r0)     * 260 + cl + 1] = f0.y + b2.y;
                        Cs[(r0 + 8) * 260 + cl]     = f1.x + b2.x;
                        Cs[(r0 + 8) * 260 + cl + 1] = f1.y + b2.y;
                    }
                }
            }
            __syncthreads();
            {
                int rr = tid >> 1, hf = tid & 1;           // 64 rows x 2 col-halves(128)
                size_t m = m0 + hblk * 64 + rr;
                const float* rsrow = resid + m * 256 + n0 + hf * 128;
                float* csrow = Cs + rr * 260 + hf * 128;
#pragma unroll
                for (int j = 0; j < 32; j++) {
                    float4 rv = *(const float4*)(rsrow + j * 4);
                    float4 cv = *(const float4*)(csrow + j * 4);
                    cv.x += rv.x; cv.y += rv.y; cv.z += rv.z; cv.w += rv.w;
                    *(float4*)(csrow + j * 4) = cv;
                }
            }
            __syncthreads();
            {
                int tok = tid & 63, sel = tid >> 6;        // 64 rows, 2-way col split
                size_t m = m0 + hblk * 64 + tok;
                int iw = (int)(m % WP_);
                size_t q = m / WP_;
                int ih = (int)(q % HP_);
                int b = (int)(q / HP_);
                if (b < B_ && ih < H_ && iw < W_) {
                    size_t base = (size_t)b * (256 * 200 * 200) + (size_t)ih * 200 + iw;
                    for (int ci = sel; ci < 256; ci += 2)
                        outf[base + (size_t)(n0 + ci) * 40000] = Cs[tok * 260 + ci];
                }
            }
        }
    }
}

// ---------------- windowed attention (register-softmax, fp16 in / f32 acc) ----------
constexpr int RPAD     = 40;
constexpr int HSTRIDE  = 49 * RPAD;
constexpr int ATTN_SMEM = (3 * 8 * HSTRIDE + 15 * RPAD) * 2;  // 95280 B -> 2 CTA/SM

__global__ void __launch_bounds__(256, 2) attn_kernel(
    const __half* __restrict__ qkv, __half* __restrict__ og)
{
    extern __shared__ char smem[];
    __half* q_s = (__half*)smem;
    __half* k_s = q_s + 8 * HSTRIDE;
    __half* v_s = k_s + 8 * HSTRIDE;

    const int win = blockIdx.x;
    const int b = win / (NWH * NWW);
    const int r = win % (NWH * NWW);
    const int wh = r / NWW, ww = r % NWW;
    const int tid = threadIdx.x;

    for (int i = tid; i < 49 * 96; i += 256) {
        int t = i / 96, ch = i % 96;
        int c0 = ch * 8;
        int ih = wh * WS_ + t / WS_, iw = ww * WS_ + t % WS_;
        size_t row = ((size_t)(b * HP_ + ih)) * WP_ + iw;
        uint4 val = *(const uint4*)(qkv + row * 768 + c0);
        int which = c0 >> 8;
        int cl = c0 & 255;
        int head = cl >> 5, d = cl & 31;
        __half* base = (which == 0) ? q_s : (which == 1) ? k_s : v_s;
        *(uint4*)(base + head * HSTRIDE + t * RPAD + d) = val;
    }
    for (int i = tid; i < 75; i += 256)
        *(uint4*)(v_s + 8 * HSTRIDE + i * 8) = make_uint4(0, 0, 0, 0);
    __syncthreads();

    const int warp = tid >> 5, lane = tid & 31;
    const int g = lane >> 2, c = lane & 3;
    const __half* qh = q_s + warp * HSTRIDE;
    const __half* kh = k_s + warp * HSTRIDE;
    const __half* vh = v_s + warp * HSTRIDE;

    unsigned kb[8][2][2];
#pragma unroll
    for (int nt = 0; nt < 8; nt++)
#pragma unroll
        for (int kc = 0; kc < 2; kc++) {
            const __half* kr = kh + (8 * nt + g) * RPAD + 16 * kc + 2 * c;
            kb[nt][kc][0] = *(const unsigned*)kr;
            kb[nt][kc][1] = *(const unsigned*)(kr + 8);
        }

    for (int rt = 0; rt < 4; rt++) {
        unsigned qa[2][4];
#pragma unroll
        for (int kc = 0; kc < 2; kc++) {
            const __half* q0 = qh + (16 * rt + g) * RPAD + 16 * kc + 2 * c;
            const __half* q1 = q0 + 8 * RPAD;
            qa[kc][0] = *(const unsigned*)q0;
            qa[kc][1] = *(const unsigned*)q1;
            qa[kc][2] = *(const unsigned*)(q0 + 8);
            qa[kc][3] = *(const unsigned*)(q1 + 8);
        }

        float sa[8][4];
#pragma unroll
        for (int nt = 0; nt < 8; nt++) { sa[nt][0] = sa[nt][1] = sa[nt][2] = sa[nt][3] = 0.f; }
#pragma unroll
        for (int nt = 0; nt < 8; nt++)
#pragma unroll
            for (int kc = 0; kc < 2; kc++)
                mma16816f(sa[nt], qa[kc][0], qa[kc][1], qa[kc][2], qa[kc][3],
                          kb[nt][kc][0], kb[nt][kc][1]);

#pragma unroll
        for (int nt = 6; nt < 8; nt++) {
            int col0 = 8 * nt + 2 * c;
            if (col0 >= 49)     { sa[nt][0] = -1e30f; sa[nt][2] = -1e30f; }
            if (col0 + 1 >= 49) { sa[nt][1] = -1e30f; sa[nt][3] = -1e30f; }
        }

        float mx0 = -1e30f, mx1 = -1e30f;
#pragma unroll
        for (int nt = 0; nt < 8; nt++) {
            mx0 = fmaxf(mx0, fmaxf(sa[nt][0], sa[nt][1]));
            mx1 = fmaxf(mx1, fmaxf(sa[nt][2], sa[nt][3]));
        }
        mx0 = fmaxf(mx0, __shfl_xor_sync(0xffffffffu, mx0, 1));
        mx0 = fmaxf(mx0, __shfl_xor_sync(0xffffffffu, mx0, 2));
        mx1 = fmaxf(mx1, __shfl_xor_sync(0xffffffffu, mx1, 1));
        mx1 = fmaxf(mx1, __shfl_xor_sync(0xffffffffu, mx1, 2));
        float sm0 = 0.f, sm1 = 0.f;
#pragma unroll
        for (int nt = 0; nt < 8; nt++) {
            sa[nt][0] = __expf(sa[nt][0] - mx0); sm0 += sa[nt][0];
            sa[nt][1] = __expf(sa[nt][1] - mx0); sm0 += sa[nt][1];
            sa[nt][2] = __expf(sa[nt][2] - mx1); sm1 += sa[nt][2];
            sa[nt][3] = __expf(sa[nt][3] - mx1); sm1 += sa[nt][3];
        }
        sm0 += __shfl_xor_sync(0xffffffffu, sm0, 1);
        sm0 += __shfl_xor_sync(0xffffffffu, sm0, 2);
        sm1 += __shfl_xor_sync(0xffffffffu, sm1, 1);
        sm1 += __shfl_xor_sync(0xffffffffu, sm1, 2);
        float inv0 = 1.f / sm0, inv1 = 1.f / sm1;

        unsigned pa[4][4];
#pragma unroll
        for (int kc = 0; kc < 4; kc++) {
            __half2 t0 = __floats2half2_rn(sa[2 * kc][0] * inv0, sa[2 * kc][1] * inv0);
            __half2 t1 = __floats2half2_rn(sa[2 * kc][2] * inv1, sa[2 * kc][3] * inv1);
            __half2 t2 = __floats2half2_rn(sa[2 * kc + 1][0] * inv0, sa[2 * kc + 1][1] * inv0);
            __half2 t3 = __floats2half2_rn(sa[2 * kc + 1][2] * inv1, sa[2 * kc + 1][3] * inv1);
            pa[kc][0] = *(unsigned*)&t0; pa[kc][1] = *(unsigned*)&t1;
            pa[kc][2] = *(unsigned*)&t2; pa[kc][3] = *(unsigned*)&t3;
        }

        float oa[4][4];
#pragma unroll
        for (int nt = 0; nt < 4; nt++) { oa[nt][0] = oa[nt][1] = oa[nt][2] = oa[nt][3] = 0.f; }
#pragma unroll
        for (int kc = 0; kc < 4; kc++)
#pragma unroll
            for (int nt = 0; nt < 4; nt++) {
                const unsigned short* vp =
                    (const unsigned short*)(vh + (16 * kc + 2 * c) * RPAD + 8 * nt + g);
                unsigned b0 = (unsigned)vp[0] | ((unsigned)vp[RPAD] << 16);
                unsigned b1 = (unsigned)vp[8 * RPAD] | ((unsigned)vp[9 * RPAD] << 16);
                mma16816f(oa[nt], pa[kc][0], pa[kc][1], pa[kc][2], pa[kc][3], b0, b1);
            }

        int t0r = 16 * rt + g, t1r = t0r + 8;
#pragma unroll
        for (int half = 0; half < 2; half++) {
            int t = half ? t1r : t0r;
            if (t < 49) {
                int ih = wh * WS_ + t / WS_, iw = ww * WS_ + t % WS_;
                size_t row = ((size_t)(b * HP_ + ih)) * WP_ + iw;
                __half* orow = og + row * 256 + warp * 32 + 2 * c;
#pragma unroll
                for (int nt = 0; nt < 4; nt++) {
                    __half2 pk2 = half
                        ? __floats2half2_rn(oa[nt][2], oa[nt][3])
                        : __floats2half2_rn(oa[nt][0], oa[nt][1]);
                    *(unsigned*)(orow + 8 * nt) = *(unsigned*)&pk2;
                }
            }
        }
    }
}

// ---------------- launch ----------------
extern "C" void kernel_launch(void* const* d_in, const int* in_sizes, int n_in,
                              void* d_out, int out_size)
{
    const float* x          = (const float*)d_in[0];
    const float* pos        = (const float*)d_in[1];
    const float* in_proj_w  = (const float*)d_in[2];
    const float* in_proj_b  = (const float*)d_in[3];
    const float* out_proj_w = (const float*)d_in[4];
    const float* out_proj_b = (const float*)d_in[5];
    const float* ln1_w      = (const float*)d_in[6];
    const float* ln1_b      = (const float*)d_in[7];
    const float* ln2_w      = (const float*)d_in[8];
    const float* ln2_b      = (const float*)d_in[9];
    const float* ff1_w      = (const float*)d_in[10];
    const float* ff1_b      = (const float*)d_in[11];
    const float* ff2_w      = (const float*)d_in[12];
    const float* ff2_b      = (const float*)d_in[13];
    float* out = (float*)d_out;

    void *p_xpad, *p_z, *p_qkv, *p_o, *p_s2, *p_h, *p_g;
    void *p_wqkv, *p_wo, *p_w1, *p_w2;
    cudaGetSymbolAddress(&p_xpad, g_xpad);
    cudaGetSymbolAddress(&p_z,    g_z);
    cudaGetSymbolAddress(&p_qkv,  g_qkv);
    cudaGetSymbolAddress(&p_o,    g_o);
    cudaGetSymbolAddress(&p_s2,   g_s2);
    cudaGetSymbolAddress(&p_h,    g_h);
    cudaGetSymbolAddress(&p_g,    g_g);
    cudaGetSymbolAddress(&p_wqkv, g_wqkv);
    cudaGetSymbolAddress(&p_wo,   g_wo);
    cudaGetSymbolAddress(&p_w1,   g_w1);
    cudaGetSymbolAddress(&p_w2,   g_w2);

    float* xpad = (float*)p_xpad;
    __half* z    = (__half*)p_z;
    __half* qkv  = (__half*)p_qkv;
    __half* o_   = (__half*)p_o;
    float* s2    = (float*)p_s2;
    __half* h_   = (__half*)p_h;
    __half* gbuf = (__half*)p_g;
    __half* wqkv = (__half*)p_wqkv;
    __half* wo   = (__half*)p_wo;
    __half* w1   = (__half*)p_w1;
    __half* w2   = (__half*)p_w2;

    cudaFuncSetAttribute(gemm_mma<0>, cudaFuncAttributeMaxDynamicSharedMemorySize, GM_SMEM);
    cudaFuncSetAttribute(gemm_mma<1>, cudaFuncAttributeMaxDynamicSharedMemorySize, GM_SMEM);
    cudaFuncSetAttribute(gemm_mma<2>, cudaFuncAttributeMaxDynamicSharedMemorySize, GM_SMEM);
    cudaFuncSetAttribute(gemm_mma<3>, cudaFuncAttributeMaxDynamicSharedMemorySize, GM_SMEM);
    cudaFuncSetAttribute(attn_kernel, cudaFuncAttributeMaxDynamicSharedMemorySize, ATTN_SMEM);

    // #0: weights -> fp16
    cvt_all_kernel<<<3072, 256>>>(in_proj_w, out_proj_w, ff1_w, ff2_w, wqkv, wo, w1, w2);

    // #1: fused pad-transpose + LN1; xpad = x+pos (fp32 residual)
    lnin_kernel<<<dim3(7, HP_, B_), dim3(32, 8)>>>(x, pos, ln1_w, ln1_b, xpad, z);

    // #2: no-op (keeps the ncu-profiled slot on the QKV GEMM)
    noop_kernel<<<1, 32>>>();

    // #3: QKV GEMM (profiled slot)
    gemm_mma<0><<<dim3(3, MTILES), 128, GM_SMEM>>>(z, wqkv, in_proj_b, 256, 768,
                                                   qkv, nullptr, nullptr);
    // #4: attention
    attn_kernel<<<NWIN, 256, ATTN_SMEM>>>(qkv, o_);

    // #5: out proj + residual(x+pos) -> s2 (fp32)
    gemm_mma<1><<<dim3(1, MTILES), 128, GM_SMEM>>>(o_, wo, out_proj_b, 256, 256,
                                                   nullptr, s2, xpad);
    // #6: LN2
    ln_kernel<<<((int)M_TOT + 7) / 8, 256>>>(s2, ln2_w, ln2_b, h_, (int)M_TOT);

    // #7: FF1 + gelu
    gemm_mma<2><<<dim3(4, MTILES), 128, GM_SMEM>>>(h_, w1, ff1_b, 256, 1024,
                                                   gbuf, nullptr, nullptr);
    // #8: FF2 + residual(s2) -> direct NCHW cropped fp32 output
    gemm_mma<3><<<dim3(1, MTILES), 128, GM_SMEM>>>(gbuf, w2, ff2_b, 1024, 256,
                                                   nullptr, out, s2);
}

// round 16
// speedup vs baseline: 1.0955x; 1.0955x over previous
#include <cuda_runtime.h>
#include <cuda_fp16.h>
#include <cstdint>
#include <math.h>

// ---------------- problem constants ----------------
constexpr int  B_   = 8;
constexpr int  C_   = 256;
constexpr int  H_   = 200;
constexpr int  W_   = 200;
constexpr int  WS_  = 7;
constexpr int  HP_  = 203;
constexpr int  WP_  = 203;
constexpr int  NWH  = 29;
constexpr int  NWW  = 29;
constexpr int  NWIN = B_ * NWH * NWW;              // 6728
constexpr size_t M_TOT = (size_t)B_ * HP_ * WP_;   // 329672 real tokens
constexpr int  MTILES = 2576;                      // ceil(M_TOT/128)
constexpr size_t M_PAD = (size_t)MTILES * 128;     // 329728 (GEMMs run guard-free)

// ---------------- scratch (device globals; zero-initialized) ----------------
__device__ float   g_xpad[M_PAD * 256];   // residual s = x + pos (fp32, channels-last)
__device__ __half  g_z   [M_PAD * 256];
__device__ __half  g_qkv [M_PAD * 768];
__device__ __half  g_o   [M_PAD * 256];
__device__ float   g_s2  [M_PAD * 256];   // s + attn proj (fp32 residual stream)
__device__ __half  g_h   [M_PAD * 256];
__device__ __half  g_g   [M_PAD * 1024];

__device__ __half  g_wqkv[768 * 256];
__device__ __half  g_wo  [256 * 256];
__device__ __half  g_w1  [1024 * 256];
__device__ __half  g_w2  [256 * 1024];

// ---------------- low-level helpers ----------------
__device__ __forceinline__ void cp16(void* s, const void* g) {
    unsigned sa = (unsigned)__cvta_generic_to_shared(s);
    asm volatile("cp.async.cg.shared.global [%0], [%1], 16;\n" :: "r"(sa), "l"(g));
}
__device__ __forceinline__ void cp_commit() { asm volatile("cp.async.commit_group;\n"); }

__device__ __forceinline__ uint32_t smem_u32(const void* p) {
    return (uint32_t)__cvta_generic_to_shared(p);
}

// fp16 in, fp16 acc
__device__ __forceinline__ void mma16816h(unsigned* d,
                                          unsigned a0, unsigned a1, unsigned a2, unsigned a3,
                                          unsigned b0, unsigned b1) {
    asm volatile("mma.sync.aligned.m16n8k16.row.col.f16.f16.f16.f16 "
                 "{%0,%1}, {%2,%3,%4,%5}, {%6,%7}, {%0,%1};"
                 : "+r"(d[0]), "+r"(d[1])
                 : "r"(a0), "r"(a1), "r"(a2), "r"(a3), "r"(b0), "r"(b1));
}

// fp16 in, fp32 acc (attention softmax path)
__device__ __forceinline__ void mma16816f(float* d,
                                          unsigned a0, unsigned a1, unsigned a2, unsigned a3,
                                          unsigned b0, unsigned b1) {
    asm volatile("mma.sync.aligned.m16n8k16.row.col.f32.f16.f16.f32 "
                 "{%0,%1,%2,%3}, {%4,%5,%6,%7}, {%8,%9}, {%0,%1,%2,%3};"
                 : "+f"(d[0]), "+f"(d[1]), "+f"(d[2]), "+f"(d[3])
                 : "r"(a0), "r"(a1), "r"(a2), "r"(a3), "r"(b0), "r"(b1));
}

__device__ __forceinline__ void ldsm_x4(unsigned& r0, unsigned& r1, unsigned& r2, unsigned& r3,
                                        uint32_t addr) {
    asm volatile("ldmatrix.sync.aligned.m8n8.x4.shared.b16 {%0,%1,%2,%3}, [%4];"
                 : "=r"(r0), "=r"(r1), "=r"(r2), "=r"(r3) : "r"(addr));
}

// ---------------- diagnostic no-op (keeps ncu's slot on the QKV GEMM) ----------
__global__ void noop_kernel() {}

// ---------------- fused fp32 -> fp16 weight convert ----------------
__global__ void cvt_all_kernel(const float* __restrict__ a0, const float* __restrict__ a1,
                               const float* __restrict__ a2, const float* __restrict__ a3,
                               __half* __restrict__ o0, __half* __restrict__ o1,
                               __half* __restrict__ o2, __half* __restrict__ o3) {
    int i = blockIdx.x * 256 + threadIdx.x;
    if (i < 196608)       o0[i] = __float2half(a0[i]);
    else if (i < 262144)  o1[i - 196608] = __float2half(a1[i - 196608]);
    else if (i < 524288)  o2[i - 262144] = __float2half(a2[i - 262144]);
    else if (i < 786432)  o3[i - 524288] = __float2half(a3[i - 524288]);
}

// ---------------- fused NCHW->channels-last pad transpose + LN1 ----------------
__global__ void __launch_bounds__(256) lnin_kernel(
    const float* __restrict__ x, const float* __restrict__ pos,
    const float* __restrict__ gw, const float* __restrict__ gb,
    float* __restrict__ xp, __half* __restrict__ z)
{
    __shared__ float tile[256][33];
    const int tx = threadIdx.x, ty = threadIdx.y;
    const int h = blockIdx.y, b = blockIdx.z;
    const int w = blockIdx.x * 32 + tx;
    const bool hv = h < H_;
    const bool wv = w < W_;
#pragma unroll
    for (int j = 0; j < 32; j++) {
        int c = ty + 8 * j;
        float v = 0.f;
        if (hv && wv) v = x[(((size_t)b * 256 + c) * 200 + h) * 200 + w];
        tile[c][tx] = v;
    }
    __syncthreads();

    const int lane = tx;
    for (int tk = ty; tk < 32; tk += 8) {
        int wtok = blockIdx.x * 32 + tk;
        if (wtok >= WP_) break;
        size_t m = ((size_t)(b * HP_ + h)) * WP_ + wtok;
        int t = (h % WS_) * WS_ + (wtok % WS_);
        float v[8];
        float s = 0.f, sq = 0.f;
#pragma unroll
        for (int i = 0; i < 8; i++) {
            int c = lane + 32 * i;
            float vv = tile[c][tk] + pos[(size_t)t * 256 + c];
            v[i] = vv;
            xp[m * 256 + c] = vv;
            s += vv; sq += vv * vv;
        }
#pragma unroll
        for (int o = 16; o; o >>= 1) {
            s  += __shfl_xor_sync(0xffffffffu, s,  o);
            sq += __shfl_xor_sync(0xffffffffu, sq, o);
        }
        float mean = s * (1.f / 256.f);
        float var  = sq * (1.f / 256.f) - mean * mean;
        float inv  = rsqrtf(var + 1e-5f);
#pragma unroll
        for (int i = 0; i < 8; i++) {
            int c = lane + 32 * i;
            z[m * 256 + c] = __float2half((v[i] - mean) * inv * gw[c] + gb[c]);
        }
    }
}

// ---------------- LayerNorm (LN2): one warp per token, fp32 in ----------------
__global__ void __launch_bounds__(256) ln_kernel(
    const float* __restrict__ in,
    const float* __restrict__ gw, const float* __restrict__ gb,
    __half* __restrict__ out, int M)
{
    int m = blockIdx.x * 8 + (threadIdx.x >> 5);
    int lane = threadIdx.x & 31;
    if (m >= M) return;
    size_t base = (size_t)m * 256 + lane * 8;
    float4 a0 = *(const float4*)(in + base);
    float4 a1 = *(const float4*)(in + base + 4);
    float v[8] = {a0.x, a0.y, a0.z, a0.w, a1.x, a1.y, a1.z, a1.w};
    float s = 0.f, sq = 0.f;
#pragma unroll
    for (int i = 0; i < 8; i++) { s += v[i]; sq += v[i] * v[i]; }
#pragma unroll
    for (int o = 16; o; o >>= 1) {
        s  += __shfl_xor_sync(0xffffffffu, s,  o);
        sq += __shfl_xor_sync(0xffffffffu, sq, o);
    }
    float mean = s * (1.f / 256.f);
    float var  = sq * (1.f / 256.f) - mean * mean;
    float inv  = rsqrtf(var + 1e-5f);
    float4 w0 = *(const float4*)(gw + lane * 8);
    float4 w1 = *(const float4*)(gw + lane * 8 + 4);
    float4 b0 = *(const float4*)(gb + lane * 8);
    float4 b1 = *(const float4*)(gb + lane * 8 + 4);
    float wv[8] = {w0.x, w0.y, w0.z, w0.w, w1.x, w1.y, w1.z, w1.w};
    float bv[8] = {b0.x, b0.y, b0.z, b0.w, b1.x, b1.y, b1.z, b1.w};
    union { uint4 u; __half h[8]; } pk;
#pragma unroll
    for (int i = 0; i < 8; i++)
        pk.h[i] = __float2half((v[i] - mean) * inv * wv[i] + bv[i]);
    *(uint4*)(out + base) = pk.u;
}

// ---------------- raw-mma fp16 GEMM  C = A(MxK) * W(NxK)^T ----------------
// CTA tile 128x128, 128 threads (4 warps; warp tile 64x64), BK=32,
// 4-stage cp.async ring (fill 3 ahead, ONE barrier per chunk), 64KB -> 3 CTA/SM.
// Rows are 64B; swizzle addr = r*64 + ((c16 ^ ((r>>1)&3))<<4) -- conflict-free
// for ldmatrix phases (r,r+1 differ in 64B half; r,r+2/r+4 differ in chunk).
constexpr int GM_STAGE = 16384;             // A 8KB + B 8KB
constexpr int GM_SMEM  = 4 * GM_STAGE;      // 65536

// EPI 0: qkv  (scale q cols, -> half)
// EPI 1: proj (acc + bias + resid(xpad f32) -> f32 s2)
// EPI 2: ff1  (gelu -> half)
// EPI 3: ff2  (acc + bias + resid(s2 f32) -> fp32 NCHW cropped out)
template <int EPI>
__global__ void __launch_bounds__(128, 3) gemm_mma(
    const __half* __restrict__ A, const __half* __restrict__ Wt,
    const float* __restrict__ bias, int K, int NOUT,
    __half* __restrict__ outb, float* __restrict__ outf,
    const float* __restrict__ resid)
{
    extern __shared__ char sm[];
    const uint32_t sb = smem_u32(sm);
    const int tid = threadIdx.x;
    const int wid = tid >> 5, lane = tid & 31;
    const int g = lane >> 2, c = lane & 3;
    const int wm = wid >> 1, wn = wid & 1;         // wm 0..1 (64 rows), wn 0..1 (64 cols)
    const int n0 = blockIdx.x * 128;
    const size_t m0 = (size_t)blockIdx.y * 128;

    const __half* gA = A + m0 * K;
    const __half* gB = Wt + (size_t)n0 * K;

    auto fill = [&](int kt, int st) {
        char* ab = sm + st * GM_STAGE;
#pragma unroll
        for (int it = 0; it < 4; it++) {          // A: 128x32 (512 16B-chunks)
            int idx = tid + it * 128;
            int r = idx >> 2, c16 = idx & 3;
            cp16(ab + r * 64 + ((c16 ^ ((r >> 1) & 3)) << 4),
                 gA + (size_t)r * K + kt * 32 + c16 * 8);
        }
#pragma unroll
        for (int it = 0; it < 4; it++) {          // B: 128x32
            int idx = tid + it * 128;
            int r = idx >> 2, c16 = idx & 3;
            cp16(ab + 8192 + r * 64 + ((c16 ^ ((r >> 1) & 3)) << 4),
                 gB + (size_t)r * K + kt * 32 + c16 * 8);
        }
        cp_commit();
    };

    unsigned acc[4][8][2];
#pragma unroll
    for (int mi = 0; mi < 4; mi++)
#pragma unroll
        for (int nt = 0; nt < 8; nt++) { acc[mi][nt][0] = 0u; acc[mi][nt][1] = 0u; }

    const int KC = K / 32;    // 8 or 32
    fill(0, 0); fill(1, 1); fill(2, 2);

    const int a_row_lo = lane & 15;
    const int a_ch_half = lane >> 4;
    const int b_tile = lane >> 3;
    const int b_row  = lane & 7;

    for (int kt = 0; kt < KC; kt++) {
        asm volatile("cp.async.wait_group 2;\n" ::: "memory");  // fill(kt) retired
        __syncthreads();           // all warps done with stage (kt-1) too
        if (kt + 3 < KC) fill(kt + 3, (kt + 3) & 3);  // writes stage (kt-1)&3: WAR-safe
        else             cp_commit();                 // empty group keeps accounting exact
        const uint32_t ab  = sb + (kt & 3) * GM_STAGE;
        const uint32_t bbm = ab + 8192;
#pragma unroll
        for (int kk = 0; kk < 2; kk++) {
            unsigned afr[4][4];
#pragma unroll
            for (int mi = 0; mi < 4; mi++) {
                int row = wm * 64 + mi * 16 + a_row_lo;
                int ch  = kk * 2 + a_ch_half;
                ldsm_x4(afr[mi][0], afr[mi][1], afr[mi][2], afr[mi][3],
                        ab + row * 64 + (uint32_t)(((ch ^ ((row >> 1) & 3)) << 4)));
            }
#pragma unroll
            for (int np = 0; np < 4; np++) {
                int n = wn * 64 + np * 16 + ((b_tile >> 1) << 3) + b_row;
                int chunk = kk * 2 + (b_tile & 1);
                unsigned bfr0, bfr1, bfr2, bfr3;
                ldsm_x4(bfr0, bfr1, bfr2, bfr3,
                        bbm + n * 64 + (uint32_t)(((chunk ^ ((n >> 1) & 3)) << 4)));
#pragma unroll
                for (int mi = 0; mi < 4; mi++) {
                    mma16816h(acc[mi][2 * np],     afr[mi][0], afr[mi][1], afr[mi][2], afr[mi][3], bfr0, bfr1);
                    mma16816h(acc[mi][2 * np + 1], afr[mi][0], afr[mi][1], afr[mi][2], afr[mi][3], bfr2, bfr3);
                }
            }
        }
    }

    // ---------- epilogues (identical to round 14) ----------
    if (EPI == 0 || EPI == 2) {
        const float scale = (EPI == 0 && n0 < 256) ? 0.17677669529663689f : 1.f;
#pragma unroll
        for (int nt = 0; nt < 8; nt++) {
            int cb = n0 + wn * 64 + nt * 8 + 2 * c;
            float2 b2 = *(const float2*)(bias + cb);
#pragma unroll
            for (int mi = 0; mi < 4; mi++) {
                size_t r0 = m0 + wm * 64 + mi * 16 + g;
#pragma unroll
                for (int half = 0; half < 2; half++) {
                    size_t r = r0 + 8 * half;
                    float2 f = __half22float2(*(__half2*)&acc[mi][nt][half]);
                    float vx = f.x + b2.x;
                    float vy = f.y + b2.y;
                    if (EPI == 0) { vx *= scale; vy *= scale; }
                    else {
                        vx = 0.5f * vx * (1.f + erff(vx * 0.7071067811865475f));
                        vy = 0.5f * vy * (1.f + erff(vy * 0.7071067811865475f));
                    }
                    __half2 pk2 = __floats2half2_rn(vx, vy);
                    *(unsigned*)(outb + r * NOUT + cb) = *(unsigned*)&pk2;
                }
            }
        }
    } else if (EPI == 1) {
#pragma unroll
        for (int mi = 0; mi < 4; mi++)
#pragma unroll
            for (int half = 0; half < 2; half++) {
                size_t m = m0 + wm * 64 + mi * 16 + g + 8 * half;
#pragma unroll
                for (int nt = 0; nt < 8; nt++) {
                    int cb = n0 + wn * 64 + nt * 8 + 2 * c;
                    float2 b2 = *(const float2*)(bias + cb);
                    float2 rs = *(const float2*)(resid + m * 256 + cb);
                    float2 f = __half22float2(*(__half2*)&acc[mi][nt][half]);
                    float2 ov;
                    ov.x = f.x + b2.x + rs.x;
                    ov.y = f.y + b2.y + rs.y;
                    *(float2*)(outf + m * 256 + cb) = ov;
                }
            }
    } else {
        // EPI 3: two 64-row halves through Cs (64 x 132 f32 = 33792 <= 64KB)
        float* Cs = (float*)sm;
#pragma unroll
        for (int hblk = 0; hblk < 2; hblk++) {
            __syncthreads();
#pragma unroll
            for (int nt = 0; nt < 8; nt++) {
                int cl = wn * 64 + nt * 8 + 2 * c;
                float2 b2 = *(const float2*)(bias + n0 + cl);
#pragma unroll
                for (int mi = 0; mi < 4; mi++) {
                    int rloc = wm * 64 + mi * 16 + g;      // 0..127 (rloc,rloc+8 same 64-block)
                    if ((rloc >> 6) == hblk) {
                        int r0 = rloc & 63;
                        float2 f0 = __half22float2(*(__half2*)&acc[mi][nt][0]);
                        float2 f1 = __half22float2(*(__half2*)&acc[mi][nt][1]);
                        Cs[(r0)     * 132 + cl]     = f0.x + b2.x;
                        Cs[(r0)     * 132 + cl + 1] = f0.y + b2.y;
                        Cs[(r0 + 8) * 132 + cl]     = f1.x + b2.x;
                        Cs[(r0 + 8) * 132 + cl + 1] = f1.y + b2.y;
                    }
                }
            }
            __syncthreads();
            {
                int rr = tid >> 1, hf = tid & 1;           // 64 rows x 2 col-halves
                size_t m = m0 + hblk * 64 + rr;
                const float* rsrow = resid + m * 256 + n0 + hf * 64;
                float* csrow = Cs + rr * 132 + hf * 64;
#pragma unroll
                for (int j = 0; j < 16; j++) {
                    float4 rv = *(const float4*)(rsrow + j * 4);
                    float4 cv = *(const float4*)(csrow + j * 4);
                    cv.x += rv.x; cv.y += rv.y; cv.z += rv.z; cv.w += rv.w;
                    *(float4*)(csrow + j * 4) = cv;
                }
            }
            __syncthreads();
            {
                int tok = tid & 63, sel = tid >> 6;        // 64 rows, 2-way col split
                size_t m = m0 + hblk * 64 + tok;
                int iw = (int)(m % WP_);
                size_t q = m / WP_;
                int ih = (int)(q % HP_);
                int b = (int)(q / HP_);
                if (b < B_ && ih < H_ && iw < W_) {
                    size_t base = (size_t)b * (256 * 200 * 200) + (size_t)ih * 200 + iw;
                    for (int ci = sel; ci < 128; ci += 2)
                        outf[base + (size_t)(n0 + ci) * 40000] = Cs[tok * 132 + ci];
                }
            }
        }
    }
}

// ---------------- windowed attention (register-softmax, fp16 in / f32 acc) ----------
constexpr int RPAD     = 40;
constexpr int HSTRIDE  = 49 * RPAD;
constexpr int ATTN_SMEM = (3 * 8 * HSTRIDE + 15 * RPAD) * 2;  // 95280 B -> 2 CTA/SM

__global__ void __launch_bounds__(256, 2) attn_kernel(
    const __half* __restrict__ qkv, __half* __restrict__ og)
{
    extern __shared__ char smem[];
    __half* q_s = (__half*)smem;
    __half* k_s = q_s + 8 * HSTRIDE;
    __half* v_s = k_s + 8 * HSTRIDE;

    const int win = blockIdx.x;
    const int b = win / (NWH * NWW);
    const int r = win % (NWH * NWW);
    const int wh = r / NWW, ww = r % NWW;
    const int tid = threadIdx.x;

    for (int i = tid; i < 49 * 96; i += 256) {
        int t = i / 96, ch = i % 96;
        int c0 = ch * 8;
        int ih = wh * WS_ + t / WS_, iw = ww * WS_ + t % WS_;
        size_t row = ((size_t)(b * HP_ + ih)) * WP_ + iw;
        uint4 val = *(const uint4*)(qkv + row * 768 + c0);
        int which = c0 >> 8;
        int cl = c0 & 255;
        int head = cl >> 5, d = cl & 31;
        __half* base = (which == 0) ? q_s : (which == 1) ? k_s : v_s;
        *(uint4*)(base + head * HSTRIDE + t * RPAD + d) = val;
    }
    for (int i = tid; i < 75; i += 256)
        *(uint4*)(v_s + 8 * HSTRIDE + i * 8) = make_uint4(0, 0, 0, 0);
    __syncthreads();

    const int warp = tid >> 5, lane = tid & 31;
    const int g = lane >> 2, c = lane & 3;
    const __half* qh = q_s + warp * HSTRIDE;
    const __half* kh = k_s + warp * HSTRIDE;
    const __half* vh = v_s + warp * HSTRIDE;

    unsigned kb[8][2][2];
#pragma unroll
    for (int nt = 0; nt < 8; nt++)
#pragma unroll
        for (int kc = 0; kc < 2; kc++) {
            const __half* kr = kh + (8 * nt + g) * RPAD + 16 * kc + 2 * c;
            kb[nt][kc][0] = *(const unsigned*)kr;
            kb[nt][kc][1] = *(const unsigned*)(kr + 8);
        }

    for (int rt = 0; rt < 4; rt++) {
        unsigned qa[2][4];
#pragma unroll
        for (int kc = 0; kc < 2; kc++) {
            const __half* q0 = qh + (16 * rt + g) * RPAD + 16 * kc + 2 * c;
            const __half* q1 = q0 + 8 * RPAD;
            qa[kc][0] = *(const unsigned*)q0;
            qa[kc][1] = *(const unsigned*)q1;
            qa[kc][2] = *(const unsigned*)(q0 + 8);
            qa[kc][3] = *(const unsigned*)(q1 + 8);
        }

        float sa[8][4];
#pragma unroll
        for (int nt = 0; nt < 8; nt++) { sa[nt][0] = sa[nt][1] = sa[nt][2] = sa[nt][3] = 0.f; }
#pragma unroll
        for (int nt = 0; nt < 8; nt++)
#pragma unroll
            for (int kc = 0; kc < 2; kc++)
                mma16816f(sa[nt], qa[kc][0], qa[kc][1], qa[kc][2], qa[kc][3],
                          kb[nt][kc][0], kb[nt][kc][1]);

#pragma unroll
        for (int nt = 6; nt < 8; nt++) {
            int col0 = 8 * nt + 2 * c;
            if (col0 >= 49)     { sa[nt][0] = -1e30f; sa[nt][2] = -1e30f; }
            if (col0 + 1 >= 49) { sa[nt][1] = -1e30f; sa[nt][3] = -1e30f; }
        }

        float mx0 = -1e30f, mx1 = -1e30f;
#pragma unroll
        for (int nt = 0; nt < 8; nt++) {
            mx0 = fmaxf(mx0, fmaxf(sa[nt][0], sa[nt][1]));
            mx1 = fmaxf(mx1, fmaxf(sa[nt][2], sa[nt][3]));
        }
        mx0 = fmaxf(mx0, __shfl_xor_sync(0xffffffffu, mx0, 1));
        mx0 = fmaxf(mx0, __shfl_xor_sync(0xffffffffu, mx0, 2));
        mx1 = fmaxf(mx1, __shfl_xor_sync(0xffffffffu, mx1, 1));
        mx1 = fmaxf(mx1, __shfl_xor_sync(0xffffffffu, mx1, 2));
        float sm0 = 0.f, sm1 = 0.f;
#pragma unroll
        for (int nt = 0; nt < 8; nt++) {
            sa[nt][0] = __expf(sa[nt][0] - mx0); sm0 += sa[nt][0];
            sa[nt][1] = __expf(sa[nt][1] - mx0); sm0 += sa[nt][1];
            sa[nt][2] = __expf(sa[nt][2] - mx1); sm1 += sa[nt][2];
            sa[nt][3] = __expf(sa[nt][3] - mx1); sm1 += sa[nt][3];
        }
        sm0 += __shfl_xor_sync(0xffffffffu, sm0, 1);
        sm0 += __shfl_xor_sync(0xffffffffu, sm0, 2);
        sm1 += __shfl_xor_sync(0xffffffffu, sm1, 1);
        sm1 += __shfl_xor_sync(0xffffffffu, sm1, 2);
        float inv0 = 1.f / sm0, inv1 = 1.f / sm1;

        unsigned pa[4][4];
#pragma unroll
        for (int kc = 0; kc < 4; kc++) {
            __half2 t0 = __floats2half2_rn(sa[2 * kc][0] * inv0, sa[2 * kc][1] * inv0);
            __half2 t1 = __floats2half2_rn(sa[2 * kc][2] * inv1, sa[2 * kc][3] * inv1);
            __half2 t2 = __floats2half2_rn(sa[2 * kc + 1][0] * inv0, sa[2 * kc + 1][1] * inv0);
            __half2 t3 = __floats2half2_rn(sa[2 * kc + 1][2] * inv1, sa[2 * kc + 1][3] * inv1);
            pa[kc][0] = *(unsigned*)&t0; pa[kc][1] = *(unsigned*)&t1;
            pa[kc][2] = *(unsigned*)&t2; pa[kc][3] = *(unsigned*)&t3;
        }

        float oa[4][4];
#pragma unroll
        for (int nt = 0; nt < 4; nt++) { oa[nt][0] = oa[nt][1] = oa[nt][2] = oa[nt][3] = 0.f; }
#pragma unroll
        for (int kc = 0; kc < 4; kc++)
#pragma unroll
            for (int nt = 0; nt < 4; nt++) {
                const unsigned short* vp =
                    (const unsigned short*)(vh + (16 * kc + 2 * c) * RPAD + 8 * nt + g);
                unsigned b0 = (unsigned)vp[0] | ((unsigned)vp[RPAD] << 16);
                unsigned b1 = (unsigned)vp[8 * RPAD] | ((unsigned)vp[9 * RPAD] << 16);
                mma16816f(oa[nt], pa[kc][0], pa[kc][1], pa[kc][2], pa[kc][3], b0, b1);
            }

        int t0r = 16 * rt + g, t1r = t0r + 8;
#pragma unroll
        for (int half = 0; half < 2; half++) {
            int t = half ? t1r : t0r;
            if (t < 49) {
                int ih = wh * WS_ + t / WS_, iw = ww * WS_ + t % WS_;
                size_t row = ((size_t)(b * HP_ + ih)) * WP_ + iw;
                __half* orow = og + row * 256 + warp * 32 + 2 * c;
#pragma unroll
                for (int nt = 0; nt < 4; nt++) {
                    __half2 pk2 = half
                        ? __floats2half2_rn(oa[nt][2], oa[nt][3])
                        : __floats2half2_rn(oa[nt][0], oa[nt][1]);
                    *(unsigned*)(orow + 8 * nt) = *(unsigned*)&pk2;
                }
            }
        }
    }
}

// ---------------- launch ----------------
extern "C" void kernel_launch(void* const* d_in, const int* in_sizes, int n_in,
                              void* d_out, int out_size)
{
    const float* x          = (const float*)d_in[0];
    const float* pos        = (const float*)d_in[1];
    const float* in_proj_w  = (const float*)d_in[2];
    const float* in_proj_b  = (const float*)d_in[3];
    const float* out_proj_w = (const float*)d_in[4];
    const float* out_proj_b = (const float*)d_in[5];
    const float* ln1_w      = (const float*)d_in[6];
    const float* ln1_b      = (const float*)d_in[7];
    const float* ln2_w      = (const float*)d_in[8];
    const float* ln2_b      = (const float*)d_in[9];
    const float* ff1_w      = (const float*)d_in[10];
    const float* ff1_b      = (const float*)d_in[11];
    const float* ff2_w      = (const float*)d_in[12];
    const float* ff2_b      = (const float*)d_in[13];
    float* out = (float*)d_out;

    void *p_xpad, *p_z, *p_qkv, *p_o, *p_s2, *p_h, *p_g;
    void *p_wqkv, *p_wo, *p_w1, *p_w2;
    cudaGetSymbolAddress(&p_xpad, g_xpad);
    cudaGetSymbolAddress(&p_z,    g_z);
    cudaGetSymbolAddress(&p_qkv,  g_qkv);
    cudaGetSymbolAddress(&p_o,    g_o);
    cudaGetSymbolAddress(&p_s2,   g_s2);
    cudaGetSymbolAddress(&p_h,    g_h);
    cudaGetSymbolAddress(&p_g,    g_g);
    cudaGetSymbolAddress(&p_wqkv, g_wqkv);
    cudaGetSymbolAddress(&p_wo,   g_wo);
    cudaGetSymbolAddress(&p_w1,   g_w1);
    cudaGetSymbolAddress(&p_w2,   g_w2);

    float* xpad = (float*)p_xpad;
    __half* z    = (__half*)p_z;
    __half* qkv  = (__half*)p_qkv;
    __half* o_   = (__half*)p_o;
    float* s2    = (float*)p_s2;
    __half* h_   = (__half*)p_h;
    __half* gbuf = (__half*)p_g;
    __half* wqkv = (__half*)p_wqkv;
    __half* wo   = (__half*)p_wo;
    __half* w1   = (__half*)p_w1;
    __half* w2   = (__half*)p_w2;

    cudaFuncSetAttribute(gemm_mma<0>, cudaFuncAttributeMaxDynamicSharedMemorySize, GM_SMEM);
    cudaFuncSetAttribute(gemm_mma<1>, cudaFuncAttributeMaxDynamicSharedMemorySize, GM_SMEM);
    cudaFuncSetAttribute(gemm_mma<2>, cudaFuncAttributeMaxDynamicSharedMemorySize, GM_SMEM);
    cudaFuncSetAttribute(gemm_mma<3>, cudaFuncAttributeMaxDynamicSharedMemorySize, GM_SMEM);
    cudaFuncSetAttribute(attn_kernel, cudaFuncAttributeMaxDynamicSharedMemorySize, ATTN_SMEM);

    // #0: weights -> fp16
    cvt_all_kernel<<<3072, 256>>>(in_proj_w, out_proj_w, ff1_w, ff2_w, wqkv, wo, w1, w2);

    // #1: fused pad-transpose + LN1; xpad = x+pos (fp32 residual)
    lnin_kernel<<<dim3(7, HP_, B_), dim3(32, 8)>>>(x, pos, ln1_w, ln1_b, xpad, z);

    // #2: no-op (keeps the ncu-profiled slot on the QKV GEMM)
    noop_kernel<<<1, 32>>>();

    // #3: QKV GEMM (profiled slot)
    gemm_mma<0><<<dim3(6, MTILES), 128, GM_SMEM>>>(z, wqkv, in_proj_b, 256, 768,
                                                   qkv, nullptr, nullptr);
    // #4: attention
    attn_kernel<<<NWIN, 256, ATTN_SMEM>>>(qkv, o_);

    // #5: out proj + residual(x+pos) -> s2 (fp32)
    gemm_mma<1><<<dim3(2, MTILES), 128, GM_SMEM>>>(o_, wo, out_proj_b, 256, 256,
                                                   nullptr, s2, xpad);
    // #6: LN2
    ln_kernel<<<((int)M_TOT + 7) / 8, 256>>>(s2, ln2_w, ln2_b, h_, (int)M_TOT);

    // #7: FF1 + gelu
    gemm_mma<2><<<dim3(8, MTILES), 128, GM_SMEM>>>(h_, w1, ff1_b, 256, 1024,
                                                   gbuf, nullptr, nullptr);
    // #8: FF2 + residual(s2) -> direct NCHW cropped fp32 output
    gemm_mma<3><<<dim3(2, MTILES), 128, GM_SMEM>>>(gbuf, w2, ff2_b, 1024, 256,
                                                   nullptr, out, s2);
}

// round 17
// speedup vs baseline: 1.1448x; 1.0450x over previous
#include <cuda_runtime.h>
#include <cuda_fp16.h>
#include <cstdint>
#include <math.h>

// ---------------- problem constants ----------------
constexpr int  B_   = 8;
constexpr int  C_   = 256;
constexpr int  H_   = 200;
constexpr int  W_   = 200;
constexpr int  WS_  = 7;
constexpr int  HP_  = 203;
constexpr int  WP_  = 203;
constexpr int  NWH  = 29;
constexpr int  NWW  = 29;
constexpr int  NWIN = B_ * NWH * NWW;              // 6728
constexpr size_t M_TOT = (size_t)B_ * HP_ * WP_;   // 329672 real tokens
constexpr int  MTILES = 2576;                      // ceil(M_TOT/128)
constexpr size_t M_PAD = (size_t)MTILES * 128;     // 329728 (GEMMs run guard-free)

// ---------------- scratch (device globals; zero-initialized) ----------------
__device__ float   g_xpad[M_PAD * 256];   // residual s = x + pos (fp32, channels-last)
__device__ __half  g_z   [M_PAD * 256];
__device__ __half  g_qkv [M_PAD * 768];
__device__ __half  g_o   [M_PAD * 256];
__device__ float   g_s2  [M_PAD * 256];   // s + attn proj (fp32 residual stream)
__device__ __half  g_h   [M_PAD * 256];
__device__ __half  g_g   [M_PAD * 1024];

__device__ __half  g_wqkv[768 * 256];
__device__ __half  g_wo  [256 * 256];
__device__ __half  g_w1  [1024 * 256];
__device__ __half  g_w2  [256 * 1024];

// ---------------- low-level helpers ----------------
__device__ __forceinline__ void cp16(void* s, const void* g) {
    unsigned sa = (unsigned)__cvta_generic_to_shared(s);
    asm volatile("cp.async.cg.shared.global [%0], [%1], 16;\n" :: "r"(sa), "l"(g));
}
__device__ __forceinline__ void cp_commit() { asm volatile("cp.async.commit_group;\n"); }
__device__ __forceinline__ void cp_wait1()  { asm volatile("cp.async.wait_group 1;\n"); }

__device__ __forceinline__ uint32_t smem_u32(const void* p) {
    return (uint32_t)__cvta_generic_to_shared(p);
}

// fp16 in, fp16 acc
__device__ __forceinline__ void mma16816h(unsigned* d,
                                          unsigned a0, unsigned a1, unsigned a2, unsigned a3,
                                          unsigned b0, unsigned b1) {
    asm volatile("mma.sync.aligned.m16n8k16.row.col.f16.f16.f16.f16 "
                 "{%0,%1}, {%2,%3,%4,%5}, {%6,%7}, {%0,%1};"
                 : "+r"(d[0]), "+r"(d[1])
                 : "r"(a0), "r"(a1), "r"(a2), "r"(a3), "r"(b0), "r"(b1));
}

// fp16 in, fp32 acc (attention softmax path)
__device__ __forceinline__ void mma16816f(float* d,
                                          unsigned a0, unsigned a1, unsigned a2, unsigned a3,
                                          unsigned b0, unsigned b1) {
    asm volatile("mma.sync.aligned.m16n8k16.row.col.f32.f16.f16.f32 "
                 "{%0,%1,%2,%3}, {%4,%5,%6,%7}, {%8,%9}, {%0,%1,%2,%3};"
                 : "+f"(d[0]), "+f"(d[1]), "+f"(d[2]), "+f"(d[3])
                 : "r"(a0), "r"(a1), "r"(a2), "r"(a3), "r"(b0), "r"(b1));
}

__device__ __forceinline__ void ldsm_x4(unsigned& r0, unsigned& r1, unsigned& r2, unsigned& r3,
                                        uint32_t addr) {
    asm volatile("ldmatrix.sync.aligned.m8n8.x4.shared.b16 {%0,%1,%2,%3}, [%4];"
                 : "=r"(r0), "=r"(r1), "=r"(r2), "=r"(r3) : "r"(addr));
}

// ---------------- diagnostic no-op (keeps ncu's slot on the QKV GEMM) ----------
__global__ void noop_kernel() {}

// ---------------- fused fp32 -> fp16 weight convert ----------------
__global__ void cvt_all_kernel(const float* __restrict__ a0, const float* __restrict__ a1,
                               const float* __restrict__ a2, const float* __restrict__ a3,
                               __half* __restrict__ o0, __half* __restrict__ o1,
                               __half* __restrict__ o2, __half* __restrict__ o3) {
    int i = blockIdx.x * 256 + threadIdx.x;
    if (i < 196608)       o0[i] = __float2half(a0[i]);
    else if (i < 262144)  o1[i - 196608] = __float2half(a1[i - 196608]);
    else if (i < 524288)  o2[i - 262144] = __float2half(a2[i - 262144]);
    else if (i < 786432)  o3[i - 524288] = __float2half(a3[i - 524288]);
}

// ---------------- fused NCHW->channels-last pad transpose + LN1 ----------------
__global__ void __launch_bounds__(256) lnin_kernel(
    const float* __restrict__ x, const float* __restrict__ pos,
    const float* __restrict__ gw, const float* __restrict__ gb,
    float* __restrict__ xp, __half* __restrict__ z)
{
    __shared__ float tile[256][33];
    const int tx = threadIdx.x, ty = threadIdx.y;
    const int h = blockIdx.y, b = blockIdx.z;
    const int w = blockIdx.x * 32 + tx;
    const bool hv = h < H_;
    const bool wv = w < W_;
#pragma unroll
    for (int j = 0; j < 32; j++) {
        int c = ty + 8 * j;
        float v = 0.f;
        if (hv && wv) v = x[(((size_t)b * 256 + c) * 200 + h) * 200 + w];
        tile[c][tx] = v;
    }
    __syncthreads();

    const int lane = tx;
    for (int tk = ty; tk < 32; tk += 8) {
        int wtok = blockIdx.x * 32 + tk;
        if (wtok >= WP_) break;
        size_t m = ((size_t)(b * HP_ + h)) * WP_ + wtok;
        int t = (h % WS_) * WS_ + (wtok % WS_);
        float v[8];
        float s = 0.f, sq = 0.f;
#pragma unroll
        for (int i = 0; i < 8; i++) {
            int c = lane + 32 * i;
            float vv = tile[c][tk] + pos[(size_t)t * 256 + c];
            v[i] = vv;
            xp[m * 256 + c] = vv;
            s += vv; sq += vv * vv;
        }
#pragma unroll
        for (int o = 16; o; o >>= 1) {
            s  += __shfl_xor_sync(0xffffffffu, s,  o);
            sq += __shfl_xor_sync(0xffffffffu, sq, o);
        }
        float mean = s * (1.f / 256.f);
        float var  = sq * (1.f / 256.f) - mean * mean;
        float inv  = rsqrtf(var + 1e-5f);
#pragma unroll
        for (int i = 0; i < 8; i++) {
            int c = lane + 32 * i;
            z[m * 256 + c] = __float2half((v[i] - mean) * inv * gw[c] + gb[c]);
        }
    }
}

// ---------------- LayerNorm (LN2): one warp per token, fp32 in ----------------
__global__ void __launch_bounds__(256) ln_kernel(
    const float* __restrict__ in,
    const float* __restrict__ gw, const float* __restrict__ gb,
    __half* __restrict__ out, int M)
{
    int m = blockIdx.x * 8 + (threadIdx.x >> 5);
    int lane = threadIdx.x & 31;
    if (m >= M) return;
    size_t base = (size_t)m * 256 + lane * 8;
    float4 a0 = *(const float4*)(in + base);
    float4 a1 = *(const float4*)(in + base + 4);
    float v[8] = {a0.x, a0.y, a0.z, a0.w, a1.x, a1.y, a1.z, a1.w};
    float s = 0.f, sq = 0.f;
#pragma unroll
    for (int i = 0; i < 8; i++) { s += v[i]; sq += v[i] * v[i]; }
#pragma unroll
    for (int o = 16; o; o >>= 1) {
        s  += __shfl_xor_sync(0xffffffffu, s,  o);
        sq += __shfl_xor_sync(0xffffffffu, sq, o);
    }
    float mean = s * (1.f / 256.f);
    float var  = sq * (1.f / 256.f) - mean * mean;
    float inv  = rsqrtf(var + 1e-5f);
    float4 w0 = *(const float4*)(gw + lane * 8);
    float4 w1 = *(const float4*)(gw + lane * 8 + 4);
    float4 b0 = *(const float4*)(gb + lane * 8);
    float4 b1 = *(const float4*)(gb + lane * 8 + 4);
    float wv[8] = {w0.x, w0.y, w0.z, w0.w, w1.x, w1.y, w1.z, w1.w};
    float bv[8] = {b0.x, b0.y, b0.z, b0.w, b1.x, b1.y, b1.z, b1.w};
    union { uint4 u; __half h[8]; } pk;
#pragma unroll
    for (int i = 0; i < 8; i++)
        pk.h[i] = __float2half((v[i] - mean) * inv * wv[i] + bv[i]);
    *(uint4*)(out + base) = pk.u;
}

// ---------------- raw-mma fp16 GEMM (round-14 proven config) ----------------
// CTA tile 128x128, 128 threads (4 warps; warp tile 64x64), BK=64,
// 2-stage cp.async double buffer, 64KB smem -> 3 CTAs/SM.
constexpr int GM_STAGE = 32768;
constexpr int GM_SMEM  = 2 * GM_STAGE;      // 65536

// EPI 0: qkv  (scale q cols, -> half)
// EPI 1: proj (acc + bias + resid(xpad f32) -> f32 s2)
// EPI 2: ff1  (gelu -> half)
// EPI 3: ff2  (acc + bias + resid(s2 f32) -> fp32 NCHW cropped out)
template <int EPI>
__global__ void __launch_bounds__(128, 3) gemm_mma(
    const __half* __restrict__ A, const __half* __restrict__ Wt,
    const float* __restrict__ bias, int K, int NOUT,
    __half* __restrict__ outb, float* __restrict__ outf,
    const float* __restrict__ resid)
{
    extern __shared__ char sm[];
    const uint32_t sb = smem_u32(sm);
    const int tid = threadIdx.x;
    const int wid = tid >> 5, lane = tid & 31;
    const int g = lane >> 2, c = lane & 3;
    const int wm = wid >> 1, wn = wid & 1;         // wm 0..1 (64 rows), wn 0..1 (64 cols)
    const int n0 = blockIdx.x * 128;
    const size_t m0 = (size_t)blockIdx.y * 128;

    const __half* gA = A + m0 * K;
    const __half* gB = Wt + (size_t)n0 * K;

    auto fill = [&](int kt, int st) {
        char* ab = sm + st * GM_STAGE;
#pragma unroll
        for (int it = 0; it < 8; it++) {          // A: 128x64 (1024 chunks)
            int idx = tid + it * 128;
            int r = idx >> 3, c16 = idx & 7;
            cp16(ab + r * 128 + ((c16 ^ (r & 7)) << 4),
                 gA + (size_t)r * K + kt * 64 + c16 * 8);
        }
#pragma unroll
        for (int it = 0; it < 8; it++) {          // B: 128x64
            int idx = tid + it * 128;
            int r = idx >> 3, c16 = idx & 7;
            cp16(ab + 16384 + r * 128 + ((c16 ^ (r & 7)) << 4),
                 gB + (size_t)r * K + kt * 64 + c16 * 8);
        }
        cp_commit();
    };

    unsigned acc[4][8][2];
#pragma unroll
    for (int mi = 0; mi < 4; mi++)
#pragma unroll
        for (int nt = 0; nt < 8; nt++) { acc[mi][nt][0] = 0u; acc[mi][nt][1] = 0u; }

    const int KC = K / 64;
    fill(0, 0); fill(1, 1);

    const int a_row_lo = lane & 15;
    const int a_ch_half = lane >> 4;
    const int b_tile = lane >> 3;
    const int b_row  = lane & 7;

    for (int kt = 0; kt < KC; kt++) {
        cp_wait1();
        __syncthreads();
        const uint32_t ab  = sb + (kt & 1) * GM_STAGE;
        const uint32_t bbm = ab + 16384;
#pragma unroll
        for (int kk = 0; kk < 4; kk++) {
            unsigned afr[4][4];
#pragma unroll
            for (int mi = 0; mi < 4; mi++) {
                int row = wm * 64 + mi * 16 + a_row_lo;
                int ch  = kk * 2 + a_ch_half;
                ldsm_x4(afr[mi][0], afr[mi][1], afr[mi][2], afr[mi][3],
                        ab + row * 128 + (uint32_t)((ch ^ (row & 7)) << 4));
            }
#pragma unroll
            for (int np = 0; np < 4; np++) {
                int n = wn * 64 + np * 16 + ((b_tile >> 1) << 3) + b_row;
                int chunk = kk * 2 + (b_tile & 1);
                unsigned bfr0, bfr1, bfr2, bfr3;
                ldsm_x4(bfr0, bfr1, bfr2, bfr3,
                        bbm + n * 128 + (uint32_t)((chunk ^ b_row) << 4));
#pragma unroll
                for (int mi = 0; mi < 4; mi++) {
                    mma16816h(acc[mi][2 * np],     afr[mi][0], afr[mi][1], afr[mi][2], afr[mi][3], bfr0, bfr1);
                    mma16816h(acc[mi][2 * np + 1], afr[mi][0], afr[mi][1], afr[mi][2], afr[mi][3], bfr2, bfr3);
                }
            }
        }
        __syncthreads();
        if (kt + 2 < KC) fill(kt + 2, kt & 1);
        else             cp_commit();              // empty group keeps accounting exact
    }

    // ---------- epilogues ----------
    if (EPI == 0 || EPI == 2) {
        const float scale = (EPI == 0 && n0 < 256) ? 0.17677669529663689f : 1.f;
#pragma unroll
        for (int nt = 0; nt < 8; nt++) {
            int cb = n0 + wn * 64 + nt * 8 + 2 * c;
            float2 b2 = *(const float2*)(bias + cb);
#pragma unroll
            for (int mi = 0; mi < 4; mi++) {
                size_t r0 = m0 + wm * 64 + mi * 16 + g;
#pragma unroll
                for (int half = 0; half < 2; half++) {
                    size_t r = r0 + 8 * half;
                    float2 f = __half22float2(*(__half2*)&acc[mi][nt][half]);
                    float vx = f.x + b2.x;
                    float vy = f.y + b2.y;
                    if (EPI == 0) { vx *= scale; vy *= scale; }
                    else {
                        vx = 0.5f * vx * (1.f + erff(vx * 0.7071067811865475f));
                        vy = 0.5f * vy * (1.f + erff(vy * 0.7071067811865475f));
                    }
                    __half2 pk2 = __floats2half2_rn(vx, vy);
                    *(unsigned*)(outb + r * NOUT + cb) = *(unsigned*)&pk2;
                }
            }
        }
    } else if (EPI == 1) {
#pragma unroll
        for (int mi = 0; mi < 4; mi++)
#pragma unroll
            for (int half = 0; half < 2; half++) {
                size_t m = m0 + wm * 64 + mi * 16 + g + 8 * half;
#pragma unroll
                for (int nt = 0; nt < 8; nt++) {
                    int cb = n0 + wn * 64 + nt * 8 + 2 * c;
                    float2 b2 = *(const float2*)(bias + cb);
                    float2 rs = *(const float2*)(resid + m * 256 + cb);
                    float2 f = __half22float2(*(__half2*)&acc[mi][nt][half]);
                    float2 ov;
                    ov.x = f.x + b2.x + rs.x;
                    ov.y = f.y + b2.y + rs.y;
                    *(float2*)(outf + m * 256 + cb) = ov;
                }
            }
    } else {
        // EPI 3: two 64-row halves through Cs (64 x 132 f32 = 33792 <= 64KB)
        float* Cs = (float*)sm;
#pragma unroll
        for (int hblk = 0; hblk < 2; hblk++) {
            __syncthreads();
#pragma unroll
            for (int nt = 0; nt < 8; nt++) {
                int cl = wn * 64 + nt * 8 + 2 * c;
                float2 b2 = *(const float2*)(bias + n0 + cl);
#pragma unroll
                for (int mi = 0; mi < 4; mi++) {
                    int rloc = wm * 64 + mi * 16 + g;      // 0..127 (rloc,rloc+8 same 64-block)
                    if ((rloc >> 6) == hblk) {
                        int r0 = rloc & 63;
                        float2 f0 = __half22float2(*(__half2*)&acc[mi][nt][0]);
                        float2 f1 = __half22float2(*(__half2*)&acc[mi][nt][1]);
                        Cs[(r0)     * 132 + cl]     = f0.x + b2.x;
                        Cs[(r0)     * 132 + cl + 1] = f0.y + b2.y;
                        Cs[(r0 + 8) * 132 + cl]     = f1.x + b2.x;
                        Cs[(r0 + 8) * 132 + cl + 1] = f1.y + b2.y;
                    }
                }
            }
            __syncthreads();
            {
                int rr = tid >> 1, hf = tid & 1;           // 64 rows x 2 col-halves
                size_t m = m0 + hblk * 64 + rr;
                const float* rsrow = resid + m * 256 + n0 + hf * 64;
                float* csrow = Cs + rr * 132 + hf * 64;
#pragma unroll
                for (int j = 0; j < 16; j++) {
                    float4 rv = *(const float4*)(rsrow + j * 4);
                    float4 cv = *(const float4*)(csrow + j * 4);
                    cv.x += rv.x; cv.y += rv.y; cv.z += rv.z; cv.w += rv.w;
                    *(float4*)(csrow + j * 4) = cv;
                }
            }
            __syncthreads();
            {
                int tok = tid & 63, sel = tid >> 6;        // 64 rows, 2-way col split
                size_t m = m0 + hblk * 64 + tok;
                int iw = (int)(m % WP_);
                size_t q = m / WP_;
                int ih = (int)(q % HP_);
                int b = (int)(q / HP_);
                if (b < B_ && ih < H_ && iw < W_) {
                    size_t base = (size_t)b * (256 * 200 * 200) + (size_t)ih * 200 + iw;
                    for (int ci = sel; ci < 128; ci += 2)
                        outf[base + (size_t)(n0 + ci) * 40000] = Cs[tok * 132 + ci];
                }
            }
        }
    }
}

// ---------------- windowed attention: Q from global (registers), K/V in smem ------
// smem 63920 B -> 3 CTA/SM (launch_bounds caps regs at 85).
constexpr int RPAD     = 40;
constexpr int HSTRIDE  = 49 * RPAD;
constexpr int ATTN_SMEM = (2 * 8 * HSTRIDE + 15 * RPAD) * 2;  // 63920 B

__global__ void __launch_bounds__(256, 3) attn_kernel(
    const __half* __restrict__ qkv, __half* __restrict__ og)
{
    extern __shared__ char smem[];
    __half* k_s = (__half*)smem;
    __half* v_s = k_s + 8 * HSTRIDE;

    const int win = blockIdx.x;
    const int b = win / (NWH * NWW);
    const int r = win % (NWH * NWW);
    const int wh = r / NWW, ww = r % NWW;
    const int tid = threadIdx.x;

    // gather 49 K/V rows (channels 256..767) into per-head compact smem
    for (int i = tid; i < 49 * 64; i += 256) {
        int t = i / 64, ch = i % 64;
        int c0 = 256 + ch * 8;
        int ih = wh * WS_ + t / WS_, iw = ww * WS_ + t % WS_;
        size_t row = ((size_t)(b * HP_ + ih)) * WP_ + iw;
        uint4 val = *(const uint4*)(qkv + row * 768 + c0);
        int cl = c0 & 255;
        int head = cl >> 5, d = cl & 31;
        __half* base = (c0 < 512) ? k_s : v_s;
        *(uint4*)(base + head * HSTRIDE + t * RPAD + d) = val;
    }
    for (int i = tid; i < 75; i += 256)
        *(uint4*)(v_s + 8 * HSTRIDE + i * 8) = make_uint4(0, 0, 0, 0);
    __syncthreads();

    const int warp = tid >> 5, lane = tid & 31;
    const int g = lane >> 2, c = lane & 3;
    const __half* kh = k_s + warp * HSTRIDE;
    const __half* vh = v_s + warp * HSTRIDE;

    unsigned kb[8][2][2];
#pragma unroll
    for (int nt = 0; nt < 8; nt++)
#pragma unroll
        for (int kc = 0; kc < 2; kc++) {
            const __half* kr = kh + (8 * nt + g) * RPAD + 16 * kc + 2 * c;
            kb[nt][kc][0] = *(const unsigned*)kr;
            kb[nt][kc][1] = *(const unsigned*)(kr + 8);
        }

    for (int rt = 0; rt < 4; rt++) {
        // ---- Q fragments straight from global (rows >= 49 clamped to 48;
        //      their S rows are computed but never stored) ----
        int t0q = 16 * rt + g;      if (t0q > 48) t0q = 48;
        int t1q = 16 * rt + g + 8;  if (t1q > 48) t1q = 48;
        size_t grow0 = ((size_t)(b * HP_ + wh * WS_ + t0q / WS_)) * WP_ + (ww * WS_ + t0q % WS_);
        size_t grow1 = ((size_t)(b * HP_ + wh * WS_ + t1q / WS_)) * WP_ + (ww * WS_ + t1q % WS_);
        const __half* q0p = qkv + grow0 * 768 + warp * 32 + 2 * c;
        const __half* q1p = qkv + grow1 * 768 + warp * 32 + 2 * c;
        unsigned qa[2][4];
#pragma unroll
        for (int kc = 0; kc < 2; kc++) {
            qa[kc][0] = *(const unsigned*)(q0p + 16 * kc);
            qa[kc][1] = *(const unsigned*)(q1p + 16 * kc);
            qa[kc][2] = *(const unsigned*)(q0p + 16 * kc + 8);
            qa[kc][3] = *(const unsigned*)(q1p + 16 * kc + 8);
        }

        float sa[8][4];
#pragma unroll
        for (int nt = 0; nt < 8; nt++) { sa[nt][0] = sa[nt][1] = sa[nt][2] = sa[nt][3] = 0.f; }
#pragma unroll
        for (int nt = 0; nt < 8; nt++)
#pragma unroll
            for (int kc = 0; kc < 2; kc++)
                mma16816f(sa[nt], qa[kc][0], qa[kc][1], qa[kc][2], qa[kc][3],
                          kb[nt][kc][0], kb[nt][kc][1]);

#pragma unroll
        for (int nt = 6; nt < 8; nt++) {
            int col0 = 8 * nt + 2 * c;
            if (col0 >= 49)     { sa[nt][0] = -1e30f; sa[nt][2] = -1e30f; }
            if (col0 + 1 >= 49) { sa[nt][1] = -1e30f; sa[nt][3] = -1e30f; }
        }

        float mx0 = -1e30f, mx1 = -1e30f;
#pragma unroll
        for (int nt = 0; nt < 8; nt++) {
            mx0 = fmaxf(mx0, fmaxf(sa[nt][0], sa[nt][1]));
            mx1 = fmaxf(mx1, fmaxf(sa[nt][2], sa[nt][3]));
        }
        mx0 = fmaxf(mx0, __shfl_xor_sync(0xffffffffu, mx0, 1));
        mx0 = fmaxf(mx0, __shfl_xor_sync(0xffffffffu, mx0, 2));
        mx1 = fmaxf(mx1, __shfl_xor_sync(0xffffffffu, mx1, 1));
        mx1 = fmaxf(mx1, __shfl_xor_sync(0xffffffffu, mx1, 2));
        float sm0 = 0.f, sm1 = 0.f;
#pragma unroll
        for (int nt = 0; nt < 8; nt++) {
            sa[nt][0] = __expf(sa[nt][0] - mx0); sm0 += sa[nt][0];
            sa[nt][1] = __expf(sa[nt][1] - mx0); sm0 += sa[nt][1];
            sa[nt][2] = __expf(sa[nt][2] - mx1); sm1 += sa[nt][2];
            sa[nt][3] = __expf(sa[nt][3] - mx1); sm1 += sa[nt][3];
        }
        sm0 += __shfl_xor_sync(0xffffffffu, sm0, 1);
        sm0 += __shfl_xor_sync(0xffffffffu, sm0, 2);
        sm1 += __shfl_xor_sync(0xffffffffu, sm1, 1);
        sm1 += __shfl_xor_sync(0xffffffffu, sm1, 2);
        float inv0 = 1.f / sm0, inv1 = 1.f / sm1;

        unsigned pa[4][4];
#pragma unroll
        for (int kc = 0; kc < 4; kc++) {
            __half2 t0 = __floats2half2_rn(sa[2 * kc][0] * inv0, sa[2 * kc][1] * inv0);
            __half2 t1 = __floats2half2_rn(sa[2 * kc][2] * inv1, sa[2 * kc][3] * inv1);
            __half2 t2 = __floats2half2_rn(sa[2 * kc + 1][0] * inv0, sa[2 * kc + 1][1] * inv0);
            __half2 t3 = __floats2half2_rn(sa[2 * kc + 1][2] * inv1, sa[2 * kc + 1][3] * inv1);
            pa[kc][0] = *(unsigned*)&t0; pa[kc][1] = *(unsigned*)&t1;
            pa[kc][2] = *(unsigned*)&t2; pa[kc][3] = *(unsigned*)&t3;
        }

        float oa[4][4];
#pragma unroll
        for (int nt = 0; nt < 4; nt++) { oa[nt][0] = oa[nt][1] = oa[nt][2] = oa[nt][3] = 0.f; }
#pragma unroll
        for (int kc = 0; kc < 4; kc++)
#pragma unroll
            for (int nt = 0; nt < 4; nt++) {
                const unsigned short* vp =
                    (const unsigned short*)(vh + (16 * kc + 2 * c) * RPAD + 8 * nt + g);
                unsigned b0 = (unsigned)vp[0] | ((unsigned)vp[RPAD] << 16);
                unsigned b1 = (unsigned)vp[8 * RPAD] | ((unsigned)vp[9 * RPAD] << 16);
                mma16816f(oa[nt], pa[kc][0], pa[kc][1], pa[kc][2], pa[kc][3], b0, b1);
            }

        int t0r = 16 * rt + g, t1r = t0r + 8;
#pragma unroll
        for (int half = 0; half < 2; half++) {
            int t = half ? t1r : t0r;
            if (t < 49) {
                int ih = wh * WS_ + t / WS_, iw = ww * WS_ + t % WS_;
                size_t row = ((size_t)(b * HP_ + ih)) * WP_ + iw;
                __half* orow = og + row * 256 + warp * 32 + 2 * c;
#pragma unroll
                for (int nt = 0; nt < 4; nt++) {
                    __half2 pk2 = half
                        ? __floats2half2_rn(oa[nt][2], oa[nt][3])
                        : __floats2half2_rn(oa[nt][0], oa[nt][1]);
                    *(unsigned*)(orow + 8 * nt) = *(unsigned*)&pk2;
                }
            }
        }
    }
}

// ---------------- launch ----------------
extern "C" void kernel_launch(void* const* d_in, const int* in_sizes, int n_in,
                              void* d_out, int out_size)
{
    const float* x          = (const float*)d_in[0];
    const float* pos        = (const float*)d_in[1];
    const float* in_proj_w  = (const float*)d_in[2];
    const float* in_proj_b  = (const float*)d_in[3];
    const float* out_proj_w = (const float*)d_in[4];
    const float* out_proj_b = (const float*)d_in[5];
    const float* ln1_w      = (const float*)d_in[6];
    const float* ln1_b      = (const float*)d_in[7];
    const float* ln2_w      = (const float*)d_in[8];
    const float* ln2_b      = (const float*)d_in[9];
    const float* ff1_w      = (const float*)d_in[10];
    const float* ff1_b      = (const float*)d_in[11];
    const float* ff2_w      = (const float*)d_in[12];
    const float* ff2_b      = (const float*)d_in[13];
    float* out = (float*)d_out;

    void *p_xpad, *p_z, *p_qkv, *p_o, *p_s2, *p_h, *p_g;
    void *p_wqkv, *p_wo, *p_w1, *p_w2;
    cudaGetSymbolAddress(&p_xpad, g_xpad);
    cudaGetSymbolAddress(&p_z,    g_z);
    cudaGetSymbolAddress(&p_qkv,  g_qkv);
    cudaGetSymbolAddress(&p_o,    g_o);
    cudaGetSymbolAddress(&p_s2,   g_s2);
    cudaGetSymbolAddress(&p_h,    g_h);
    cudaGetSymbolAddress(&p_g,    g_g);
    cudaGetSymbolAddress(&p_wqkv, g_wqkv);
    cudaGetSymbolAddress(&p_wo,   g_wo);
    cudaGetSymbolAddress(&p_w1,   g_w1);
    cudaGetSymbolAddress(&p_w2,   g_w2);

    float* xpad = (float*)p_xpad;
    __half* z    = (__half*)p_z;
    __half* qkv  = (__half*)p_qkv;
    __half* o_   = (__half*)p_o;
    float* s2    = (float*)p_s2;
    __half* h_   = (__half*)p_h;
    __half* gbuf = (__half*)p_g;
    __half* wqkv = (__half*)p_wqkv;
    __half* wo   = (__half*)p_wo;
    __half* w1   = (__half*)p_w1;
    __half* w2   = (__half*)p_w2;

    cudaFuncSetAttribute(gemm_mma<0>, cudaFuncAttributeMaxDynamicSharedMemorySize, GM_SMEM);
    cudaFuncSetAttribute(gemm_mma<1>, cudaFuncAttributeMaxDynamicSharedMemorySize, GM_SMEM);
    cudaFuncSetAttribute(gemm_mma<2>, cudaFuncAttributeMaxDynamicSharedMemorySize, GM_SMEM);
    cudaFuncSetAttribute(gemm_mma<3>, cudaFuncAttributeMaxDynamicSharedMemorySize, GM_SMEM);
    cudaFuncSetAttribute(attn_kernel, cudaFuncAttributeMaxDynamicSharedMemorySize, ATTN_SMEM);

    // #0: weights -> fp16
    cvt_all_kernel<<<3072, 256>>>(in_proj_w, out_proj_w, ff1_w, ff2_w, wqkv, wo, w1, w2);

    // #1: fused pad-transpose + LN1; xpad = x+pos (fp32 residual)
    lnin_kernel<<<dim3(7, HP_, B_), dim3(32, 8)>>>(x, pos, ln1_w, ln1_b, xpad, z);

    // #2: no-op (keeps the ncu-profiled slot on the QKV GEMM)
    noop_kernel<<<1, 32>>>();

    // #3: QKV GEMM (profiled slot)
    gemm_mma<0><<<dim3(6, MTILES), 128, GM_SMEM>>>(z, wqkv, in_proj_b, 256, 768,
                                                   qkv, nullptr, nullptr);
    // #4: attention
    attn_kernel<<<NWIN, 256, ATTN_SMEM>>>(qkv, o_);

    // #5: out proj + residual(x+pos) -> s2 (fp32)
    gemm_mma<1><<<dim3(2, MTILES), 128, GM_SMEM>>>(o_, wo, out_proj_b, 256, 256,
                                                   nullptr, s2, xpad);
    // #6: LN2
    ln_kernel<<<((int)M_TOT + 7) / 8, 256>>>(s2, ln2_w, ln2_b, h_, (int)M_TOT);

    // #7: FF1 + gelu
    gemm_mma<2><<<dim3(8, MTILES), 128, GM_SMEM>>>(h_, w1, ff1_b, 256, 1024,
                                                   gbuf, nullptr, nullptr);
    // #8: FF2 + residual(s2) -> direct NCHW cropped fp32 output
    gemm_mma<3><<<dim3(2, MTILES), 128, GM_SMEM>>>(gbuf, w2, ff2_b, 1024, 256,
                                                   nullptr, out, s2);
}